// round 9
// baseline (speedup 1.0000x reference)
#include <cuda_runtime.h>
#include <cuda_bf16.h>

// y[t, f] = x[t, f] * w[f] + b[f]
// x: [8192, 4096] f32 (128 MiB), w/b: [4096] f32, out: same shape.
//
// Pure HBM streaming. Measured ladder on sm_103a:
//  - LDG.128 is the right width (v8 loads tank L1tex: 66us).
//  - L2-residency games lose (R4).
//  - ILP=2: 39.0 -> 36.1us.  ILP=4: -> 35.3us (6.05 TB/s, 75.7%).
// This round: ILP=8 split-eighth mapping — 8 independent front-batched
// LDG.128 per thread, same column for all (w/b loaded once). Trades some
// occupancy (regs ~52) for deeper aggregate request depth.

#define TOKENS      8192
#define IN_FEATURES 4096
#define COLS4       (IN_FEATURES / 4)    // 1024, pow2
#define N4          (TOKENS * COLS4)     // 8,388,608 quads
#define SEG         (N4 / 8)             // 1,048,576 (multiple of COLS4)

__global__ __launch_bounds__(256) void one_to_one_kernel(
    const float4* __restrict__ x,
    const float4* __restrict__ w,
    const float4* __restrict__ b,
    float4* __restrict__ out)
{
    int i = blockIdx.x * blockDim.x + threadIdx.x;   // 0 .. SEG-1
    int c = i & (COLS4 - 1);                         // same column for all 8 quads

    // Eight independent streaming loads, front-batched for deep MLP
    float4 xv[8];
#pragma unroll
    for (int k = 0; k < 8; k++)
        xv[k] = x[i + k * SEG];

    float4 wv = __ldg(&w[c]);
    float4 bv = __ldg(&b[c]);

#pragma unroll
    for (int k = 0; k < 8; k++) {
        float4 r;
        r.x = fmaf(xv[k].x, wv.x, bv.x);
        r.y = fmaf(xv[k].y, wv.y, bv.y);
        r.z = fmaf(xv[k].z, wv.z, bv.z);
        r.w = fmaf(xv[k].w, wv.w, bv.w);
        out[i + k * SEG] = r;
    }
}

extern "C" void kernel_launch(void* const* d_in, const int* in_sizes, int n_in,
                              void* d_out, int out_size)
{
    const float4* x = (const float4*)d_in[0];
    const float4* w = (const float4*)d_in[1];
    const float4* b = (const float4*)d_in[2];
    float4* out = (float4*)d_out;

    const int threads = 256;
    const int blocks  = SEG / threads;   // 4096
    one_to_one_kernel<<<blocks, threads>>>(x, w, b, out);
}

// round 11
// speedup vs baseline: 1.0463x; 1.0463x over previous
#include <cuda_runtime.h>
#include <cuda_bf16.h>

// y[t, f] = x[t, f] * w[f] + b[f]
// x: [8192, 4096] f32 (128 MiB), w/b: [4096] f32, out: same shape.
//
// Pure HBM streaming. Measured ladder on sm_103a:
//  - LDG.128 is the right width (v8 loads tank L1tex: 66us).
//  - L2-residency games lose (R4).
//  - ILP=2: 36.1us. ILP=4: 35.3us (6.05 TB/s). ILP=8: 39.8us (occ+L1tex loss).
// ILP=4 is the MLP/occupancy ridge. This round: launch-shape microtune only,
// block 256 -> 512 (fewer CTAs, smoother per-SM wave balance).

#define TOKENS      8192
#define IN_FEATURES 4096
#define COLS4       (IN_FEATURES / 4)    // 1024, pow2
#define N4          (TOKENS * COLS4)     // 8,388,608 quads
#define Q4          (N4 / 4)             // 2,097,152 (multiple of COLS4)

__global__ __launch_bounds__(512) void one_to_one_kernel(
    const float4* __restrict__ x,
    const float4* __restrict__ w,
    const float4* __restrict__ b,
    float4* __restrict__ out)
{
    int i = blockIdx.x * blockDim.x + threadIdx.x;   // 0 .. Q4-1
    int c = i & (COLS4 - 1);                         // same column for all 4 quads

    // Four independent streaming loads, front-batched for deep MLP
    float4 x0 = x[i];
    float4 x1 = x[i + Q4];
    float4 x2 = x[i + 2 * Q4];
    float4 x3 = x[i + 3 * Q4];

    float4 wv = __ldg(&w[c]);
    float4 bv = __ldg(&b[c]);

    float4 r0, r1, r2, r3;
    r0.x = fmaf(x0.x, wv.x, bv.x); r0.y = fmaf(x0.y, wv.y, bv.y);
    r0.z = fmaf(x0.z, wv.z, bv.z); r0.w = fmaf(x0.w, wv.w, bv.w);
    r1.x = fmaf(x1.x, wv.x, bv.x); r1.y = fmaf(x1.y, wv.y, bv.y);
    r1.z = fmaf(x1.z, wv.z, bv.z); r1.w = fmaf(x1.w, wv.w, bv.w);
    r2.x = fmaf(x2.x, wv.x, bv.x); r2.y = fmaf(x2.y, wv.y, bv.y);
    r2.z = fmaf(x2.z, wv.z, bv.z); r2.w = fmaf(x2.w, wv.w, bv.w);
    r3.x = fmaf(x3.x, wv.x, bv.x); r3.y = fmaf(x3.y, wv.y, bv.y);
    r3.z = fmaf(x3.z, wv.z, bv.z); r3.w = fmaf(x3.w, wv.w, bv.w);

    out[i]          = r0;
    out[i + Q4]     = r1;
    out[i + 2 * Q4] = r2;
    out[i + 3 * Q4] = r3;
}

extern "C" void kernel_launch(void* const* d_in, const int* in_sizes, int n_in,
                              void* d_out, int out_size)
{
    const float4* x = (const float4*)d_in[0];
    const float4* w = (const float4*)d_in[1];
    const float4* b = (const float4*)d_in[2];
    float4* out = (float4*)d_out;

    const int threads = 512;
    const int blocks  = Q4 / threads;   // 4096
    one_to_one_kernel<<<blocks, threads>>>(x, w, b, out);
}

// round 12
// speedup vs baseline: 1.0471x; 1.0007x over previous
#include <cuda_runtime.h>
#include <cuda_bf16.h>

// y[t, f] = x[t, f] * w[f] + b[f]
// x: [8192, 4096] f32 (128 MiB), w/b: [4096] f32, out: same shape.
//
// Pure HBM streaming. Measured ladder on sm_103a:
//  - LDG.128 is the right width (v8 loads tank L1tex: 66us).
//  - L2-residency pinning loses (R4). ILP ridge is 4 (36.1/35.3/39.8).
//  - Block 512 no better than 256 (35.8 vs 35.3).
// This round: isolated cache-policy test on the ILP=4/256 winner —
// ld.global.cs for x, st.global.cs for out (both streams are no-reuse;
// stop write-allocate churn in L2, keep sectors for write batching).

#define TOKENS      8192
#define IN_FEATURES 4096
#define COLS4       (IN_FEATURES / 4)    // 1024, pow2
#define N4          (TOKENS * COLS4)     // 8,388,608 quads
#define Q4          (N4 / 4)             // 2,097,152 (multiple of COLS4)

__device__ __forceinline__ float4 ldg_cs(const float4* p) {
    float4 v;
    asm("ld.global.cs.v4.f32 {%0,%1,%2,%3}, [%4];"
        : "=f"(v.x), "=f"(v.y), "=f"(v.z), "=f"(v.w)
        : "l"(p));
    return v;
}

__device__ __forceinline__ void stg_cs(float4* p, float4 v) {
    asm volatile("st.global.cs.v4.f32 [%0], {%1,%2,%3,%4};"
                 :: "l"(p), "f"(v.x), "f"(v.y), "f"(v.z), "f"(v.w)
                 : "memory");
}

__global__ __launch_bounds__(256) void one_to_one_kernel(
    const float4* __restrict__ x,
    const float4* __restrict__ w,
    const float4* __restrict__ b,
    float4* __restrict__ out)
{
    int i = blockIdx.x * blockDim.x + threadIdx.x;   // 0 .. Q4-1
    int c = i & (COLS4 - 1);                         // same column for all 4 quads

    // Four independent streaming loads, front-batched for deep MLP
    float4 x0 = ldg_cs(&x[i]);
    float4 x1 = ldg_cs(&x[i + Q4]);
    float4 x2 = ldg_cs(&x[i + 2 * Q4]);
    float4 x3 = ldg_cs(&x[i + 3 * Q4]);

    float4 wv = __ldg(&w[c]);
    float4 bv = __ldg(&b[c]);

    float4 r0, r1, r2, r3;
    r0.x = fmaf(x0.x, wv.x, bv.x); r0.y = fmaf(x0.y, wv.y, bv.y);
    r0.z = fmaf(x0.z, wv.z, bv.z); r0.w = fmaf(x0.w, wv.w, bv.w);
    r1.x = fmaf(x1.x, wv.x, bv.x); r1.y = fmaf(x1.y, wv.y, bv.y);
    r1.z = fmaf(x1.z, wv.z, bv.z); r1.w = fmaf(x1.w, wv.w, bv.w);
    r2.x = fmaf(x2.x, wv.x, bv.x); r2.y = fmaf(x2.y, wv.y, bv.y);
    r2.z = fmaf(x2.z, wv.z, bv.z); r2.w = fmaf(x2.w, wv.w, bv.w);
    r3.x = fmaf(x3.x, wv.x, bv.x); r3.y = fmaf(x3.y, wv.y, bv.y);
    r3.z = fmaf(x3.z, wv.z, bv.z); r3.w = fmaf(x3.w, wv.w, bv.w);

    stg_cs(&out[i],          r0);
    stg_cs(&out[i + Q4],     r1);
    stg_cs(&out[i + 2 * Q4], r2);
    stg_cs(&out[i + 3 * Q4], r3);
}

extern "C" void kernel_launch(void* const* d_in, const int* in_sizes, int n_in,
                              void* d_out, int out_size)
{
    const float4* x = (const float4*)d_in[0];
    const float4* w = (const float4*)d_in[1];
    const float4* b = (const float4*)d_in[2];
    float4* out = (float4*)d_out;

    const int threads = 256;
    const int blocks  = Q4 / threads;   // 8192
    one_to_one_kernel<<<blocks, threads>>>(x, w, b, out);
}